// round 8
// baseline (speedup 1.0000x reference)
#include <cuda_runtime.h>
#include <cuda_bf16.h>
#include <math.h>
#include <stdint.h>

#define NUMS  128
#define BATCH 256
#define HCH   64
#define DIM   32
#define HID   256
#define XDIM  65
#define KW    32
#define DT    (1.0f/128.0f)
#define GRID  132
#define TPB   256
#define GSIZE 33            // blocks per independent group

#define AP_B 528            // A/B smem row stride in bytes (264 bf16)

// smem byte offsets
#define OFF_AHI  0                       // 64 x 528B = 33792
#define OFF_ALO  33792
#define OFF_BHI  67584                   // 64 x 528B (W2 slice, K-contig)
#define OFF_BLO  101376
#define OFF_OS   135168                  // 64 x 68 f32 = 17408
#define OFF_DB   152576                  // 64 x 33 f32 = 8448
#define OFF_BIAS 161024                  // 64 f32
#define OFF_XS   161280                  // 2 x 65 f32
#define OFF_KWV  161808                  // 128 f32
#define OFF_KSV  162320                  // 128 f32
#define OFF_RED  162832                  // 256 f32
#define SMEM_BYTES 163856

// ---------------- device scratch ----------------
__device__ float d_gvals[NUMS + 1];
__device__ float d_kmu[NUMS + 1];
__device__ float d_ksig[NUMS + 1];
__device__ uint4 d_Hhi4[BATCH * 64];    // 256 rows x 512 bf16-hi
__device__ uint4 d_Hlo4[BATCH * 64];
__device__ float d_muh[NUMS * BATCH * HCH];
__device__ float d_svh[NUMS * BATCH * HCH];
__device__ unsigned d_bars[256];        // 4 group counters, 256B apart (idx g<<6)

// ---------------- init ----------------
__global__ void init_kernel(const float* gw1, const float* gb1, const float* gw2, const float* gb2,
                            const float* mw1, const float* mb1, const float* mw2, const float* mb2,
                            const float* sw1, const float* sb1, const float* sw2, const float* sb2)
{
    int t = threadIdx.x;
    if (t < 256) d_bars[t] = 0u;
    if (t <= NUMS) {
        float tt = t * DT;
        float a = gb2[0], b = mb2[0], c = sb2[0];
        for (int k = 0; k < KW; ++k) {
            a += tanhf(tt * gw1[k] + gb1[k]) * gw2[k];
            b += tanhf(tt * mw1[k] + mb1[k]) * mw2[k];
            c += tanhf(tt * sw1[k] + sb1[k]) * sw2[k];
        }
        d_gvals[t] = a; d_kmu[t] = b; d_ksig[t] = c;
    }
}

// ---------------- helpers ----------------
static __device__ __forceinline__ uint32_t s2u(const void* p) {
    uint32_t a;
    asm("{ .reg .u64 t; cvta.to.shared.u64 t, %1; cvt.u32.u64 %0, t; }" : "=r"(a) : "l"(p));
    return a;
}
static __device__ __forceinline__ void gbar(unsigned* ctr, unsigned target) {
    __syncthreads();
    if (threadIdx.x == 0) {
        asm volatile("red.release.gpu.global.add.u32 [%0], 1;" :: "l"(ctr) : "memory");
        unsigned v;
        do {
            asm volatile("ld.acquire.gpu.global.u32 %0, [%1];" : "=r"(v) : "l"(ctr) : "memory");
        } while ((int)(v - target) < 0);
    }
    __syncthreads();
}
static __device__ __forceinline__ void ldsm4(uint32_t addr, uint32_t* r) {
    asm volatile("ldmatrix.sync.aligned.m8n8.x4.shared.b16 {%0,%1,%2,%3}, [%4];"
                 : "=r"(r[0]), "=r"(r[1]), "=r"(r[2]), "=r"(r[3]) : "r"(addr));
}
static __device__ __forceinline__ void mma16816(float* c, const uint32_t* a,
                                                uint32_t b0, uint32_t b1) {
    asm volatile("mma.sync.aligned.m16n8k16.row.col.f32.bf16.bf16.f32 "
                 "{%0,%1,%2,%3}, {%4,%5,%6,%7}, {%8,%9}, {%0,%1,%2,%3};"
                 : "+f"(c[0]), "+f"(c[1]), "+f"(c[2]), "+f"(c[3])
                 : "r"(a[0]), "r"(a[1]), "r"(a[2]), "r"(a[3]), "r"(b0), "r"(b1));
}
static __device__ __forceinline__ unsigned packbf(float x, float y) {
    __nv_bfloat16 bx = __float2bfloat16(x), by = __float2bfloat16(y);
    return ((unsigned)__bfloat16_as_ushort(by) << 16) | __bfloat16_as_ushort(bx);
}

// ---------------- persistent solver ----------------
__global__ void __launch_bounds__(TPB, 1) solve(
    const float* __restrict__ Bin, const float* __restrict__ z0,
    const float* __restrict__ muw1, const float* __restrict__ mub1,
    const float* __restrict__ muw2, const float* __restrict__ mub2,
    const float* __restrict__ sgw1, const float* __restrict__ sgb1,
    const float* __restrict__ sgw2, const float* __restrict__ sgb2,
    float* __restrict__ out)
{
    extern __shared__ __align__(16) char sm[];
    uint32_t smb = s2u(sm);
    float* Osm   = (float*)(sm + OFF_OS);
    float* dBs   = (float*)(sm + OFF_DB);
    float* biasS = (float*)(sm + OFF_BIAS);
    float* xs    = (float*)(sm + OFF_XS);
    float* kwv   = (float*)(sm + OFF_KWV);
    float* ksv   = (float*)(sm + OFF_KSV);
    float* red   = (float*)(sm + OFF_RED);

    int bk = blockIdx.x, t = threadIdx.x;
    int wid = t >> 5, lane = t & 31;

    bool is_sig = (bk < 128);
    int grp  = is_sig ? (bk >> 5) : (bk - 128);
    int b0g  = grp * 64;
    int cb   = is_sig ? (bk & 31) : 0;
    int col0 = cb * 64;
    const float* W2  = is_sig ? sgw2 : muw2;
    const float* B2b = is_sig ? (sgb2 + col0) : mub2;
    int ldw   = is_sig ? (HCH * DIM) : HCH;
    int hofs4 = is_sig ? 32 : 0;

    unsigned* ctr = &d_bars[grp << 6];
    unsigned target = 0;

    if (t < 64) biasS[t] = B2b[t];

    // ---- B (W2 slice) hi/lo into smem ONCE, [n][k] K-contiguous ----
    for (int idx = t; idx < 64 * 256; idx += TPB) {
        int n = idx & 63, k = idx >> 6;
        float wv = W2[(size_t)k * ldw + col0 + n];
        __nv_bfloat16 h = __float2bfloat16(wv);
        float lo = wv - __bfloat162float(h);
        uint32_t o = (uint32_t)n * AP_B + (uint32_t)k * 2;
        *(__nv_bfloat16*)(sm + OFF_BHI + o) = h;
        *(__nv_bfloat16*)(sm + OFF_BLO + o) = __float2bfloat16(lo);
    }

    int wc = wid & 3, wr = wid >> 2;     // warp: 4 col-groups x 2 row-groups
    int convb0 = bk * 2;
    uint32_t aBaseHi = smb + OFF_AHI + (wr * 32 + (lane & 15)) * AP_B + ((lane >> 4) * 8) * 2;
    uint32_t aBaseLo = aBaseHi + (uint32_t)(OFF_ALO - OFF_AHI);
    uint32_t bBaseHi = smb + OFF_BHI
                     + (uint32_t)(wc * 16 + (lane & 7) + ((lane >> 4) << 3)) * AP_B
                     + ((lane >> 3) & 1) * 16;
    uint32_t bBaseLo = bBaseHi + (uint32_t)(OFF_BLO - OFF_BHI);

    for (int j = 0; j < NUMS; ++j) {
        // ========== phase 1: conv -> S_j, MLP1 -> packed hi/lo H, dB staging ==========
        if (is_sig) {
            if (t < j) { kwv[t] = DT * d_kmu[j - t]; ksv[t] = d_ksig[j - t]; }
            if (t < 2) xs[t * XDIM] = j * DT;
            __syncthreads();

            int e = t & 127, p = t >> 7;
            float acc = 0.f;
            int base = convb0 * HCH + e;
            #pragma unroll 4
            for (int m = p; m < j; m += 2)
                acc += kwv[m] * d_muh[m * (BATCH * HCH) + base]
                     + ksv[m] * d_svh[m * (BATCH * HCH) + base];
            red[t] = acc;
            __syncthreads();

            if (t < 128) {
                float s = red[t] + red[t + 128];
                float z = z0[convb0 * HCH + t];
                float S = z * d_gvals[j] + s;
                out[(size_t)j * (BATCH * HCH) + convb0 * HCH + t] = S;
                xs[(t >> 6) * XDIM + 1 + (t & 63)] = (j == 0) ? z : S;
            }
            __syncthreads();

            // MLP1: row r, 4 cols of combined 512 hidden
            int r = t >> 7, ci = t & 127, c4 = ci * 4;
            const float* w1; const float* b1; int cc;
            if (c4 < 256) { w1 = muw1; b1 = mub1; cc = c4; }
            else          { w1 = sgw1; b1 = sgb1; cc = c4 - 256; }
            float4 a = *(const float4*)&b1[cc];
            #pragma unroll 5
            for (int i = 0; i < XDIM; ++i) {
                float4 wv = *(const float4*)&w1[i * HID + cc];
                float xv = xs[r * XDIM + i];
                a.x += xv * wv.x; a.y += xv * wv.y; a.z += xv * wv.z; a.w += xv * wv.w;
            }
            float v0 = tanhf(a.x), v1 = tanhf(a.y), v2 = tanhf(a.z), v3 = tanhf(a.w);
            __nv_bfloat16 h0 = __float2bfloat16(v0), h1 = __float2bfloat16(v1);
            __nv_bfloat16 h2 = __float2bfloat16(v2), h3 = __float2bfloat16(v3);
            uint2 hp, lp;
            hp.x = ((unsigned)__bfloat16_as_ushort(h1) << 16) | __bfloat16_as_ushort(h0);
            hp.y = ((unsigned)__bfloat16_as_ushort(h3) << 16) | __bfloat16_as_ushort(h2);
            lp.x = packbf(v0 - __bfloat162float(h0), v1 - __bfloat162float(h1));
            lp.y = packbf(v2 - __bfloat162float(h2), v3 - __bfloat162float(h3));
            int rowi = (convb0 + r) * 256 + ci * 2;
            *(uint2*)((unsigned*)d_Hhi4 + rowi) = hp;
            *(uint2*)((unsigned*)d_Hlo4 + rowi) = lp;

            // dB staging for this step (independent of phase boundary)
            {
                int row = t >> 2, c = (t & 3) * 8;
                const float* src = &Bin[(size_t)(b0g + row) * ((NUMS + 1) * DIM)
                                        + (size_t)(j + 1) * DIM + c];
                float4 u0 = *(const float4*)src;
                float4 u1 = *(const float4*)(src + 4);
                if (j > 0) {
                    float4 p0 = *(const float4*)(src - DIM);
                    float4 p1 = *(const float4*)(src - DIM + 4);
                    u0.x -= p0.x; u0.y -= p0.y; u0.z -= p0.z; u0.w -= p0.w;
                    u1.x -= p1.x; u1.y -= p1.y; u1.z -= p1.z; u1.w -= p1.w;
                }
                dBs[row * 33 + c + 0] = u0.x; dBs[row * 33 + c + 1] = u0.y;
                dBs[row * 33 + c + 2] = u0.z; dBs[row * 33 + c + 3] = u0.w;
                dBs[row * 33 + c + 4] = u1.x; dBs[row * 33 + c + 5] = u1.y;
                dBs[row * 33 + c + 6] = u1.z; dBs[row * 33 + c + 7] = u1.w;
            }
        }
        gbar(ctr, target += GSIZE);

        // ========== phase 2: HMMA GEMM (64 x 64, K=256, 3-pass split-bf16) ==========
        {   // A staging: H tile [64 x 256] hi+lo
            int row = t & 63, part = t >> 6;
            int isLo = part >> 1, half = part & 1;
            const uint4* src = (isLo ? d_Hlo4 : d_Hhi4)
                               + (b0g + row) * 64 + hofs4 + half * 16;
            char* dst = sm + (isLo ? OFF_ALO : OFF_AHI) + row * AP_B + half * 256;
            #pragma unroll 4
            for (int it = 0; it < 16; ++it) {
                uint4 v = __ldcg(src + it);
                *(uint4*)(dst + it * 16) = v;
            }
        }
        __syncthreads();

        float acc[2][2][4];
        #pragma unroll
        for (int mt = 0; mt < 2; ++mt)
            #pragma unroll
            for (int nt = 0; nt < 2; ++nt)
                #pragma unroll
                for (int q = 0; q < 4; ++q) acc[mt][nt][q] = 0.f;

        #pragma unroll 4
        for (int kt = 0; kt < 16; ++kt) {
            uint32_t ah[2][4], al[2][4], bh[4], bl[4];
            ldsm4(bBaseHi + kt * 32, bh);
            ldsm4(bBaseLo + kt * 32, bl);
            #pragma unroll
            for (int mt = 0; mt < 2; ++mt) {
                ldsm4(aBaseHi + mt * (16 * AP_B) + kt * 32, ah[mt]);
                ldsm4(aBaseLo + mt * (16 * AP_B) + kt * 32, al[mt]);
            }
            #pragma unroll
            for (int mt = 0; mt < 2; ++mt)
                #pragma unroll
                for (int nt = 0; nt < 2; ++nt) {
                    mma16816(acc[mt][nt], ah[mt], bh[nt * 2], bh[nt * 2 + 1]);
                    mma16816(acc[mt][nt], ah[mt], bl[nt * 2], bl[nt * 2 + 1]);
                    mma16816(acc[mt][nt], al[mt], bh[nt * 2], bh[nt * 2 + 1]);
                }
        }

        // ---- epilogue: O tile to smem (+bias) ----
        __syncthreads();
        {
            int rb = wr * 32 + (lane >> 2);
            int cbc = wc * 16 + (lane & 3) * 2;
            #pragma unroll
            for (int mt = 0; mt < 2; ++mt)
                #pragma unroll
                for (int nt = 0; nt < 2; ++nt) {
                    int row0 = rb + mt * 16, col = cbc + nt * 8;
                    Osm[row0 * 68 + col]           = acc[mt][nt][0] + biasS[col];
                    Osm[row0 * 68 + col + 1]       = acc[mt][nt][1] + biasS[col + 1];
                    Osm[(row0 + 8) * 68 + col]     = acc[mt][nt][2] + biasS[col];
                    Osm[(row0 + 8) * 68 + col + 1] = acc[mt][nt][3] + biasS[col + 1];
                }
        }
        __syncthreads();

        if (is_sig) {
            if (t < 128) {
                int row = t >> 1, hh = t & 1;
                const float* orow = &Osm[row * 68 + hh * 32];
                const float* drow = &dBs[row * 33];
                float s = 0.f;
                #pragma unroll 8
                for (int d = 0; d < 32; ++d) s = fmaf(orow[d], drow[d], s);
                d_svh[(size_t)j * (BATCH * HCH) + (b0g + row) * HCH + cb * 2 + hh] = s;
            }
        } else {
            int row = t >> 2, c0m = (t & 3) * 16;
            float* dst = &d_muh[(size_t)j * (BATCH * HCH) + (b0g + row) * HCH + c0m];
            #pragma unroll
            for (int q = 0; q < 4; ++q)
                *(float4*)(dst + q * 4) = *(const float4*)&Osm[row * 68 + c0m + q * 4];
        }
        gbar(ctr, target += GSIZE);
    }

    // ---- final output row 128 (conv only) ----
    if (is_sig) {
        if (t < 128) { kwv[t] = DT * d_kmu[NUMS - t]; ksv[t] = d_ksig[NUMS - t]; }
        __syncthreads();
        int e = t & 127, p = t >> 7;
        float acc = 0.f;
        int base = convb0 * HCH + e;
        #pragma unroll 4
        for (int m = p; m < NUMS; m += 2)
            acc += kwv[m] * d_muh[m * (BATCH * HCH) + base]
                 + ksv[m] * d_svh[m * (BATCH * HCH) + base];
        red[t] = acc;
        __syncthreads();
        if (t < 128) {
            float s = red[t] + red[t + 128];
            float z = z0[convb0 * HCH + t];
            out[(size_t)NUMS * (BATCH * HCH) + convb0 * HCH + t] = z * d_gvals[NUMS] + s;
        }
    }
}

// ---------------- launch ----------------
extern "C" void kernel_launch(void* const* d_in, const int* in_sizes, int n_in,
                              void* d_out, int out_size)
{
    const float* B    = (const float*)d_in[0];
    const float* z0   = (const float*)d_in[1];
    const float* gw1  = (const float*)d_in[6];
    const float* gb1  = (const float*)d_in[7];
    const float* gw2  = (const float*)d_in[8];
    const float* gb2  = (const float*)d_in[9];
    const float* kmw1 = (const float*)d_in[10];
    const float* kmb1 = (const float*)d_in[11];
    const float* kmw2 = (const float*)d_in[12];
    const float* kmb2 = (const float*)d_in[13];
    const float* ksw1 = (const float*)d_in[14];
    const float* ksb1 = (const float*)d_in[15];
    const float* ksw2 = (const float*)d_in[16];
    const float* ksb2 = (const float*)d_in[17];
    const float* muw1 = (const float*)d_in[18];
    const float* mub1 = (const float*)d_in[19];
    const float* muw2 = (const float*)d_in[20];
    const float* mub2 = (const float*)d_in[21];
    const float* sgw1 = (const float*)d_in[22];
    const float* sgb1 = (const float*)d_in[23];
    const float* sgw2 = (const float*)d_in[24];
    const float* sgb2 = (const float*)d_in[25];
    float* out = (float*)d_out;

    cudaFuncSetAttribute(solve, cudaFuncAttributeMaxDynamicSharedMemorySize, SMEM_BYTES);

    init_kernel<<<1, 256>>>(gw1, gb1, gw2, gb2, kmw1, kmb1, kmw2, kmb2,
                            ksw1, ksb1, ksw2, ksb2);
    solve<<<GRID, TPB, SMEM_BYTES>>>(B, z0, muw1, mub1, muw2, mub2,
                                     sgw1, sgb1, sgw2, sgb2, out);
}

// round 9
// speedup vs baseline: 1.5577x; 1.5577x over previous
#include <cuda_runtime.h>
#include <cuda_bf16.h>
#include <math.h>
#include <stdint.h>

#define NUMS  128
#define BATCH 256
#define HCH   64
#define DIM   32
#define HID   256
#define XDIM  65
#define KW    32
#define DT    (1.0f/128.0f)
#define GRID  132
#define TPB   512

#define AP_B 528            // A smem row stride in bytes (264 bf16)

// smem byte offsets
#define OFF_AHI  0                       // 64 x 528B = 33792
#define OFF_ALO  33792
#define OFF_OS   67584                   // 64 x 68 f32 = 17408
#define OFF_DB   84992                   // 64 x 33 f32 = 8448
#define OFF_BIAS 93440                   // 64 f32
#define OFF_XS   93696                   // 2 x 65 f32 (pad to 528)
#define OFF_KWV  94224                   // 128 f32
#define OFF_KSV  94736                   // 128 f32
#define OFF_RED  95248                   // 512 f32
#define SMEM_BYTES 97296

// ---------------- device scratch ----------------
__device__ float d_gvals[NUMS + 1];
__device__ float d_kmu[NUMS + 1];
__device__ float d_ksig[NUMS + 1];
__device__ uint4 d_Hhi4[BATCH * 64];    // 256 rows x 512 bf16-hi (u32-packed pairs)
__device__ uint4 d_Hlo4[BATCH * 64];
__device__ float d_muh[NUMS * BATCH * HCH];
__device__ float d_svh[NUMS * BATCH * HCH];
__device__ unsigned d_bar;

// ---------------- init ----------------
__global__ void init_kernel(const float* gw1, const float* gb1, const float* gw2, const float* gb2,
                            const float* mw1, const float* mb1, const float* mw2, const float* mb2,
                            const float* sw1, const float* sb1, const float* sw2, const float* sb2)
{
    int t = threadIdx.x;
    if (t == 0) d_bar = 0u;
    if (t <= NUMS) {
        float tt = t * DT;
        float a = gb2[0], b = mb2[0], c = sb2[0];
        for (int k = 0; k < KW; ++k) {
            a += tanhf(tt * gw1[k] + gb1[k]) * gw2[k];
            b += tanhf(tt * mw1[k] + mb1[k]) * mw2[k];
            c += tanhf(tt * sw1[k] + sb1[k]) * sw2[k];
        }
        d_gvals[t] = a; d_kmu[t] = b; d_ksig[t] = c;
    }
}

// ---------------- helpers ----------------
static __device__ __forceinline__ uint32_t s2u(const void* p) {
    uint32_t a;
    asm("{ .reg .u64 t; cvta.to.shared.u64 t, %1; cvt.u32.u64 %0, t; }" : "=r"(a) : "l"(p));
    return a;
}
static __device__ __forceinline__ void gbar(unsigned target) {
    __syncthreads();
    if (threadIdx.x == 0) {
        unsigned* p = &d_bar;
        asm volatile("red.release.gpu.global.add.u32 [%0], 1;" :: "l"(p) : "memory");
        unsigned v;
        do {
            asm volatile("ld.acquire.gpu.global.u32 %0, [%1];" : "=r"(v) : "l"(p) : "memory");
        } while ((int)(v - target) < 0);
    }
    __syncthreads();
}
static __device__ __forceinline__ void ldsm4(uint32_t addr, uint32_t* r) {
    asm volatile("ldmatrix.sync.aligned.m8n8.x4.shared.b16 {%0,%1,%2,%3}, [%4];"
                 : "=r"(r[0]), "=r"(r[1]), "=r"(r[2]), "=r"(r[3]) : "r"(addr));
}
static __device__ __forceinline__ void mma16816(float* c, const uint32_t* a,
                                                uint32_t b0, uint32_t b1) {
    asm volatile("mma.sync.aligned.m16n8k16.row.col.f32.bf16.bf16.f32 "
                 "{%0,%1,%2,%3}, {%4,%5,%6,%7}, {%8,%9}, {%0,%1,%2,%3};"
                 : "+f"(c[0]), "+f"(c[1]), "+f"(c[2]), "+f"(c[3])
                 : "r"(a[0]), "r"(a[1]), "r"(a[2]), "r"(a[3]), "r"(b0), "r"(b1));
}
static __device__ __forceinline__ unsigned packbf(float x, float y) {
    __nv_bfloat16 bx = __float2bfloat16(x), by = __float2bfloat16(y);
    return ((unsigned)__bfloat16_as_ushort(by) << 16) | __bfloat16_as_ushort(bx);
}

// ---------------- persistent solver ----------------
__global__ void __launch_bounds__(TPB, 1) solve(
    const float* __restrict__ Bin, const float* __restrict__ z0,
    const float* __restrict__ muw1, const float* __restrict__ mub1,
    const float* __restrict__ muw2, const float* __restrict__ mub2,
    const float* __restrict__ sgw1, const float* __restrict__ sgb1,
    const float* __restrict__ sgw2, const float* __restrict__ sgb2,
    float* __restrict__ out)
{
    extern __shared__ __align__(16) char sm[];
    uint32_t smb = s2u(sm);
    float* Osm   = (float*)(sm + OFF_OS);
    float* dBs   = (float*)(sm + OFF_DB);
    float* biasS = (float*)(sm + OFF_BIAS);
    float* xs    = (float*)(sm + OFF_XS);
    float* kwv   = (float*)(sm + OFF_KWV);
    float* ksv   = (float*)(sm + OFF_KSV);
    float* red   = (float*)(sm + OFF_RED);

    int bk = blockIdx.x, t = threadIdx.x;
    int wid = t >> 5, lane = t & 31;
    unsigned target = 0;

    bool is_sig = (bk < 128);
    int b0g  = is_sig ? (bk >> 5) * 64 : (bk - 128) * 64;
    int cb   = is_sig ? (bk & 31) : 0;
    int col0 = cb * 64;
    const float* W2  = is_sig ? sgw2 : muw2;
    const float* B2b = is_sig ? (sgb2 + col0) : mub2;
    int ldw   = is_sig ? (HCH * DIM) : HCH;
    int hofs4 = is_sig ? 32 : 0;

    if (t < 64) biasS[t] = B2b[t];

    // ---- warp mapping: 2 K-halves x (4 col-groups x 2 row-groups) ----
    int kh   = wid >> 3;                 // 0: kt 0-7, 1: kt 8-15
    int wsub = wid & 7;
    int wc = wsub & 3, wr = wsub >> 2;

    // ---- B fragments (W2 slice) in registers, hi/lo, this K-half only ----
    unsigned Bhi[8][2][2], Blo[8][2][2];
    {
        int nb = col0 + wc * 16 + (lane >> 2);
        #pragma unroll
        for (int kt = 0; kt < 8; ++kt)
            #pragma unroll
            for (int nt = 0; nt < 2; ++nt)
                #pragma unroll
                for (int rr = 0; rr < 2; ++rr) {
                    int k0 = (kh * 8 + kt) * 16 + (lane & 3) * 2 + rr * 8;
                    int n  = nb + nt * 8;
                    float w0 = W2[(size_t)k0 * ldw + n];
                    float w1 = W2[(size_t)(k0 + 1) * ldw + n];
                    __nv_bfloat16 h0 = __float2bfloat16(w0);
                    __nv_bfloat16 h1 = __float2bfloat16(w1);
                    float l0 = w0 - __bfloat162float(h0);
                    float l1 = w1 - __bfloat162float(h1);
                    Bhi[kt][nt][rr] = ((unsigned)__bfloat16_as_ushort(h1) << 16)
                                    | __bfloat16_as_ushort(h0);
                    Blo[kt][nt][rr] = packbf(l0, l1);
                }
    }

    int convb0 = bk * 2;
    uint32_t aBaseHi = smb + OFF_AHI + (wr * 32 + (lane & 15)) * AP_B + ((lane >> 4) * 8) * 2;
    uint32_t aBaseLo = aBaseHi + (uint32_t)(OFF_ALO - OFF_AHI);

    for (int j = 0; j < NUMS; ++j) {
        // ========== phase 1: conv -> S_j, MLP1 -> packed hi/lo H ==========
        if (is_sig) {
            if (t < j) { kwv[t] = DT * d_kmu[j - t]; ksv[t] = d_ksig[j - t]; }
            if (t < 2) xs[t * XDIM] = j * DT;
            __syncthreads();

            int e = t & 127, p = t >> 7;     // 4-way k-split
            float acc = 0.f;
            int base = convb0 * HCH + e;
            #pragma unroll 4
            for (int m = p; m < j; m += 4)
                acc += kwv[m] * d_muh[m * (BATCH * HCH) + base]
                     + ksv[m] * d_svh[m * (BATCH * HCH) + base];
            red[t] = acc;
            __syncthreads();

            if (t < 128) {
                float s = red[t] + red[t + 128] + red[t + 256] + red[t + 384];
                float z = z0[convb0 * HCH + t];
                float S = z * d_gvals[j] + s;
                out[(size_t)j * (BATCH * HCH) + convb0 * HCH + t] = S;
                xs[(t >> 6) * XDIM + 1 + (t & 63)] = (j == 0) ? z : S;
            }
            __syncthreads();

            // MLP1: thread -> row r (0/1), 2 cols of combined 512 hidden
            int r = t >> 8, ci = t & 255, c2 = ci * 2;
            const float* w1; const float* b1; int cc;
            if (c2 < 256) { w1 = muw1; b1 = mub1; cc = c2; }
            else          { w1 = sgw1; b1 = sgb1; cc = c2 - 256; }
            float ax = b1[cc], ay = b1[cc + 1];
            #pragma unroll 5
            for (int i = 0; i < XDIM; ++i) {
                float2 wv = *(const float2*)&w1[i * HID + cc];
                float xv = xs[r * XDIM + i];
                ax = fmaf(xv, wv.x, ax);
                ay = fmaf(xv, wv.y, ay);
            }
            float v0 = tanhf(ax), v1 = tanhf(ay);
            __nv_bfloat16 h0 = __float2bfloat16(v0), h1 = __float2bfloat16(v1);
            unsigned hp = ((unsigned)__bfloat16_as_ushort(h1) << 16) | __bfloat16_as_ushort(h0);
            unsigned lp = packbf(v0 - __bfloat162float(h0), v1 - __bfloat162float(h1));
            int rowi = (convb0 + r) * 256 + ci;
            ((unsigned*)d_Hhi4)[rowi] = hp;
            ((unsigned*)d_Hlo4)[rowi] = lp;
        }
        gbar(target += GRID);

        // ========== phase 2: HMMA GEMM (64 x 64, K=256, split-K x 2 warpsets) ==========
        if (is_sig) {   // dB staging
            int row = t >> 3, c = (t & 7) * 4;
            const float* src = &Bin[(size_t)(b0g + row) * ((NUMS + 1) * DIM)
                                    + (size_t)(j + 1) * DIM + c];
            float4 v = *(const float4*)src;
            if (j > 0) {
                float4 u = *(const float4*)(src - DIM);
                v.x -= u.x; v.y -= u.y; v.z -= u.z; v.w -= u.w;
            }
            dBs[row * 33 + c + 0] = v.x; dBs[row * 33 + c + 1] = v.y;
            dBs[row * 33 + c + 2] = v.z; dBs[row * 33 + c + 3] = v.w;
        }
        {   // A staging: H tile [64 x 256] hi+lo bf16 -> smem (8 parts of 128B)
            int row = t & 63, part = t >> 6;
            int isLo = part >> 2, quarter = part & 3;
            const uint4* src = (isLo ? d_Hlo4 : d_Hhi4)
                               + (b0g + row) * 64 + hofs4 + quarter * 8;
            char* dst = sm + (isLo ? OFF_ALO : OFF_AHI) + row * AP_B + quarter * 128;
            #pragma unroll
            for (int it = 0; it < 8; ++it) {
                uint4 v = __ldcg(src + it);
                *(uint4*)(dst + it * 16) = v;
            }
        }
        __syncthreads();

        float acc[2][2][4];
        #pragma unroll
        for (int mt = 0; mt < 2; ++mt)
            #pragma unroll
            for (int nt = 0; nt < 2; ++nt)
                #pragma unroll
                for (int q = 0; q < 4; ++q) acc[mt][nt][q] = 0.f;

        #pragma unroll
        for (int kt = 0; kt < 8; ++kt) {
            int ktg = kh * 8 + kt;
            uint32_t ah[2][4], al[2][4];
            #pragma unroll
            for (int mt = 0; mt < 2; ++mt) {
                ldsm4(aBaseHi + mt * (16 * AP_B) + ktg * 32, ah[mt]);
                ldsm4(aBaseLo + mt * (16 * AP_B) + ktg * 32, al[mt]);
            }
            #pragma unroll
            for (int mt = 0; mt < 2; ++mt)
                #pragma unroll
                for (int nt = 0; nt < 2; ++nt) {
                    mma16816(acc[mt][nt], ah[mt], Bhi[kt][nt][0], Bhi[kt][nt][1]);
                    mma16816(acc[mt][nt], ah[mt], Blo[kt][nt][0], Blo[kt][nt][1]);
                    mma16816(acc[mt][nt], al[mt], Bhi[kt][nt][0], Bhi[kt][nt][1]);
                }
        }

        // ---- split-K combine through Osm ----
        int rb  = wr * 32 + (lane >> 2);
        int cbc = wc * 16 + (lane & 3) * 2;
        if (kh == 0) {
            #pragma unroll
            for (int mt = 0; mt < 2; ++mt)
                #pragma unroll
                for (int nt = 0; nt < 2; ++nt) {
                    int row0 = rb + mt * 16, col = cbc + nt * 8;
                    Osm[row0 * 68 + col]           = acc[mt][nt][0] + biasS[col];
                    Osm[row0 * 68 + col + 1]       = acc[mt][nt][1] + biasS[col + 1];
                    Osm[(row0 + 8) * 68 + col]     = acc[mt][nt][2] + biasS[col];
                    Osm[(row0 + 8) * 68 + col + 1] = acc[mt][nt][3] + biasS[col + 1];
                }
        }
        __syncthreads();
        if (kh == 1) {
            #pragma unroll
            for (int mt = 0; mt < 2; ++mt)
                #pragma unroll
                for (int nt = 0; nt < 2; ++nt) {
                    int row0 = rb + mt * 16, col = cbc + nt * 8;
                    Osm[row0 * 68 + col]           += acc[mt][nt][0];
                    Osm[row0 * 68 + col + 1]       += acc[mt][nt][1];
                    Osm[(row0 + 8) * 68 + col]     += acc[mt][nt][2];
                    Osm[(row0 + 8) * 68 + col + 1] += acc[mt][nt][3];
                }
        }
        __syncthreads();

        if (is_sig) {
            if (t < 128) {
                int row = t >> 1, hh = t & 1;
                const float* orow = &Osm[row * 68 + hh * 32];
                const float* drow = &dBs[row * 33];
                float s = 0.f;
                #pragma unroll 8
                for (int d = 0; d < 32; ++d) s = fmaf(orow[d], drow[d], s);
                d_svh[(size_t)j * (BATCH * HCH) + (b0g + row) * HCH + cb * 2 + hh] = s;
            }
        } else {
            int row = t >> 3, c0m = (t & 7) * 8;
            float* dst = &d_muh[(size_t)j * (BATCH * HCH) + (b0g + row) * HCH + c0m];
            *(float4*)dst       = *(const float4*)&Osm[row * 68 + c0m];
            *(float4*)(dst + 4) = *(const float4*)&Osm[row * 68 + c0m + 4];
        }
        gbar(target += GRID);
    }

    // ---- final output row 128 (conv only) ----
    if (is_sig) {
        if (t < 128) { kwv[t] = DT * d_kmu[NUMS - t]; ksv[t] = d_ksig[NUMS - t]; }
        __syncthreads();
        int e = t & 127, p = t >> 7;
        float acc = 0.f;
        int base = convb0 * HCH + e;
        #pragma unroll 4
        for (int m = p; m < NUMS; m += 4)
            acc += kwv[m] * d_muh[m * (BATCH * HCH) + base]
                 + ksv[m] * d_svh[m * (BATCH * HCH) + base];
        red[t] = acc;
        __syncthreads();
        if (t < 128) {
            float s = red[t] + red[t + 128] + red[t + 256] + red[t + 384];
            float z = z0[convb0 * HCH + t];
            out[(size_t)NUMS * (BATCH * HCH) + convb0 * HCH + t] = z * d_gvals[NUMS] + s;
        }
    }
}

// ---------------- launch ----------------
extern "C" void kernel_launch(void* const* d_in, const int* in_sizes, int n_in,
                              void* d_out, int out_size)
{
    const float* B    = (const float*)d_in[0];
    const float* z0   = (const float*)d_in[1];
    const float* gw1  = (const float*)d_in[6];
    const float* gb1  = (const float*)d_in[7];
    const float* gw2  = (const float*)d_in[8];
    const float* gb2  = (const float*)d_in[9];
    const float* kmw1 = (const float*)d_in[10];
    const float* kmb1 = (const float*)d_in[11];
    const float* kmw2 = (const float*)d_in[12];
    const float* kmb2 = (const float*)d_in[13];
    const float* ksw1 = (const float*)d_in[14];
    const float* ksb1 = (const float*)d_in[15];
    const float* ksw2 = (const float*)d_in[16];
    const float* ksb2 = (const float*)d_in[17];
    const float* muw1 = (const float*)d_in[18];
    const float* mub1 = (const float*)d_in[19];
    const float* muw2 = (const float*)d_in[20];
    const float* mub2 = (const float*)d_in[21];
    const float* sgw1 = (const float*)d_in[22];
    const float* sgb1 = (const float*)d_in[23];
    const float* sgw2 = (const float*)d_in[24];
    const float* sgb2 = (const float*)d_in[25];
    float* out = (float*)d_out;

    cudaFuncSetAttribute(solve, cudaFuncAttributeMaxDynamicSharedMemorySize, SMEM_BYTES);

    init_kernel<<<1, 256>>>(gw1, gb1, gw2, gb2, kmw1, kmb1, kmw2, kmb2,
                            ksw1, ksb1, ksw2, ksb2);
    solve<<<GRID, TPB, SMEM_BYTES>>>(B, z0, muw1, mub1, muw2, mub2,
                                     sgw1, sgb1, sgw2, sgb2, out);
}

// round 13
// speedup vs baseline: 1.5742x; 1.0106x over previous
#include <cuda_runtime.h>
#include <cuda_bf16.h>
#include <math.h>
#include <stdint.h>

#define NUMS  128
#define BATCH 256
#define HCH   64
#define DIM   32
#define HID   256
#define XDIM  65
#define KW    32
#define DT    (1.0f/128.0f)
#define GRID  132
#define TPB   512

#define AP_B 528            // A smem row stride in bytes (264 bf16)

// smem byte offsets
#define OFF_W1   0                       // 65 x 512 f32 = 133120 (combined mu|sig w1)
#define OFF_AHI  133120                  // 64 x 528B = 33792
#define OFF_ALO  166912
#define OFF_OS   200704                  // 64 x 68 f32 = 17408
#define OFF_DB   218112                  // 64 x 33 f32 = 8448
#define OFF_BIAS 226560                  // 64 f32
#define SMEM_BYTES 226816
// phase-1 scratch overlaid into the Osm region (time-disjoint with Osm)
#define OFF_XS   (OFF_OS + 0)            // 2 x 68 f32 = 544
#define OFF_KWV  (OFF_OS + 1024)         // 128 f32
#define OFF_KSV  (OFF_OS + 1536)         // 128 f32
#define OFF_RED  (OFF_OS + 2048)         // 512 f32 -> ends OS+4096

// ---------------- device scratch ----------------
__device__ float d_gvals[NUMS + 1];
__device__ float d_kmu[NUMS + 1];
__device__ float d_ksig[NUMS + 1];
__device__ uint4 d_Hhi4[BATCH * 64];    // 256 rows x 512 bf16-hi
__device__ uint4 d_Hlo4[BATCH * 64];
__device__ float d_muh[NUMS * BATCH * HCH];
__device__ float d_svh[NUMS * BATCH * HCH];
__device__ unsigned d_bar;

// ---------------- init ----------------
__global__ void init_kernel(const float* gw1, const float* gb1, const float* gw2, const float* gb2,
                            const float* mw1, const float* mb1, const float* mw2, const float* mb2,
                            const float* sw1, const float* sb1, const float* sw2, const float* sb2)
{
    int t = threadIdx.x;
    if (t == 0) d_bar = 0u;
    if (t <= NUMS) {
        float tt = t * DT;
        float a = gb2[0], b = mb2[0], c = sb2[0];
        for (int k = 0; k < KW; ++k) {
            a += tanhf(tt * gw1[k] + gb1[k]) * gw2[k];
            b += tanhf(tt * mw1[k] + mb1[k]) * mw2[k];
            c += tanhf(tt * sw1[k] + sb1[k]) * sw2[k];
        }
        d_gvals[t] = a; d_kmu[t] = b; d_ksig[t] = c;
    }
}

// ---------------- helpers ----------------
static __device__ __forceinline__ uint32_t s2u(const void* p) {
    uint32_t a;
    asm("{ .reg .u64 t; cvta.to.shared.u64 t, %1; cvt.u32.u64 %0, t; }" : "=r"(a) : "l"(p));
    return a;
}
static __device__ __forceinline__ void gbar(unsigned target) {
    __syncthreads();
    if (threadIdx.x == 0) {
        unsigned* p = &d_bar;
        asm volatile("red.release.gpu.global.add.u32 [%0], 1;" :: "l"(p) : "memory");
        unsigned v;
        do {
            asm volatile("ld.acquire.gpu.global.u32 %0, [%1];" : "=r"(v) : "l"(p) : "memory");
        } while ((int)(v - target) < 0);
    }
    __syncthreads();
}
static __device__ __forceinline__ void ldsm4(uint32_t addr, uint32_t* r) {
    asm volatile("ldmatrix.sync.aligned.m8n8.x4.shared.b16 {%0,%1,%2,%3}, [%4];"
                 : "=r"(r[0]), "=r"(r[1]), "=r"(r[2]), "=r"(r[3]) : "r"(addr));
}
static __device__ __forceinline__ void mma16816(float* c, const uint32_t* a,
                                                uint32_t b0, uint32_t b1) {
    asm volatile("mma.sync.aligned.m16n8k16.row.col.f32.bf16.bf16.f32 "
                 "{%0,%1,%2,%3}, {%4,%5,%6,%7}, {%8,%9}, {%0,%1,%2,%3};"
                 : "+f"(c[0]), "+f"(c[1]), "+f"(c[2]), "+f"(c[3])
                 : "r"(a[0]), "r"(a[1]), "r"(a[2]), "r"(a[3]), "r"(b0), "r"(b1));
}
static __device__ __forceinline__ unsigned packbf(float x, float y) {
    __nv_bfloat16 bx = __float2bfloat16(x), by = __float2bfloat16(y);
    return ((unsigned)__bfloat16_as_ushort(by) << 16) | __bfloat16_as_ushort(bx);
}

// ---------------- persistent solver ----------------
__global__ void __launch_bounds__(TPB, 1) solve(
    const float* __restrict__ Bin, const float* __restrict__ z0,
    const float* __restrict__ muw1, const float* __restrict__ mub1,
    const float* __restrict__ muw2, const float* __restrict__ mub2,
    const float* __restrict__ sgw1, const float* __restrict__ sgb1,
    const float* __restrict__ sgw2, const float* __restrict__ sgb2,
    float* __restrict__ out)
{
    extern __shared__ __align__(16) char sm[];
    uint32_t smb = s2u(sm);
    float* w1s   = (float*)(sm + OFF_W1);
    float* Osm   = (float*)(sm + OFF_OS);
    float* dBs   = (float*)(sm + OFF_DB);
    float* biasS = (float*)(sm + OFF_BIAS);
    float* xs    = (float*)(sm + OFF_XS);
    float* kwv   = (float*)(sm + OFF_KWV);
    float* ksv   = (float*)(sm + OFF_KSV);
    float* red   = (float*)(sm + OFF_RED);

    int bk = blockIdx.x, t = threadIdx.x;
    int wid = t >> 5, lane = t & 31;
    unsigned target = 0;

    bool is_sig = (bk < 128);
    int b0g  = is_sig ? (bk >> 5) * 64 : (bk - 128) * 64;
    int cb   = is_sig ? (bk & 31) : 0;
    int col0 = cb * 64;
    const float* W2  = is_sig ? sgw2 : muw2;
    const float* B2b = is_sig ? (sgb2 + col0) : mub2;
    int ldw   = is_sig ? (HCH * DIM) : HCH;
    int hofs4 = is_sig ? 32 : 0;

    if (t < 64) biasS[t] = B2b[t];

    // ---- w1 (mu|sig combined) into smem ONCE ----
    for (int idx = t; idx < 65 * 512; idx += TPB) {
        int i = idx >> 9, c = idx & 511;
        w1s[idx] = (c < 256) ? muw1[i * 256 + c] : sgw1[i * 256 + (c - 256)];
    }
    // per-thread MLP1 constants (col = t)
    float b1c = (t < 256) ? mub1[t] : sgb1[t - 256];

    // ---- warp mapping: 2 K-halves x (4 col-groups x 2 row-groups) ----
    int kh   = wid >> 3;
    int wsub = wid & 7;
    int wc = wsub & 3, wr = wsub >> 2;

    // ---- B fragments (W2 slice) in registers, hi/lo, this K-half only ----
    unsigned Bhi[8][2][2], Blo[8][2][2];
    {
        int nb = col0 + wc * 16 + (lane >> 2);
        #pragma unroll
        for (int kt = 0; kt < 8; ++kt)
            #pragma unroll
            for (int nt = 0; nt < 2; ++nt)
                #pragma unroll
                for (int rr = 0; rr < 2; ++rr) {
                    int k0 = (kh * 8 + kt) * 16 + (lane & 3) * 2 + rr * 8;
                    int n  = nb + nt * 8;
                    float w0 = W2[(size_t)k0 * ldw + n];
                    float w1 = W2[(size_t)(k0 + 1) * ldw + n];
                    __nv_bfloat16 h0 = __float2bfloat16(w0);
                    __nv_bfloat16 h1 = __float2bfloat16(w1);
                    float l0 = w0 - __bfloat162float(h0);
                    float l1 = w1 - __bfloat162float(h1);
                    Bhi[kt][nt][rr] = ((unsigned)__bfloat16_as_ushort(h1) << 16)
                                    | __bfloat16_as_ushort(h0);
                    Blo[kt][nt][rr] = packbf(l0, l1);
                }
    }

    int convb0 = bk * 2;
    uint32_t aBaseHi = smb + OFF_AHI + (wr * 32 + (lane & 15)) * AP_B + ((lane >> 4) * 8) * 2;
    uint32_t aBaseLo = aBaseHi + (uint32_t)(OFF_ALO - OFF_AHI);

    for (int j = 0; j < NUMS; ++j) {
        // ========== phase 1: conv -> S_j, MLP1 -> packed hi/lo H ==========
        if (is_sig) {
            if (t < j) { kwv[t] = DT * d_kmu[j - t]; ksv[t] = d_ksig[j - t]; }
            if (t < 2) xs[t * 68] = j * DT;
            __syncthreads();

            int e = t & 127, p = t >> 7;     // 4-way k-split
            float acc = 0.f;
            int base = convb0 * HCH + e;
            #pragma unroll 4
            for (int m = p; m < j; m += 4)
                acc += kwv[m] * d_muh[m * (BATCH * HCH) + base]
                     + ksv[m] * d_svh[m * (BATCH * HCH) + base];
            red[t] = acc;
            __syncthreads();

            if (t < 128) {
                float s = red[t] + red[t + 128] + red[t + 256] + red[t + 384];
                float z = z0[convb0 * HCH + t];
                float S = z * d_gvals[j] + s;
                out[(size_t)j * (BATCH * HCH) + convb0 * HCH + t] = S;
                xs[(t >> 6) * 68 + 1 + (t & 63)] = (j == 0) ? z : S;
            }
            __syncthreads();

            // MLP1: thread t -> combined col t (0..511), BOTH rows (w1 read once)
            {
                const float* wcol = w1s + t;
                float a0 = b1c, a1 = b1c;
                #pragma unroll
                for (int i4 = 0; i4 < 64; i4 += 4) {
                    float4 x0 = *(const float4*)&xs[i4];
                    float4 x1 = *(const float4*)&xs[68 + i4];
                    float w0 = wcol[(i4 + 0) * 512];
                    float w1v = wcol[(i4 + 1) * 512];
                    float w2v = wcol[(i4 + 2) * 512];
                    float w3v = wcol[(i4 + 3) * 512];
                    a0 = fmaf(x0.x, w0, a0); a1 = fmaf(x1.x, w0, a1);
                    a0 = fmaf(x0.y, w1v, a0); a1 = fmaf(x1.y, w1v, a1);
                    a0 = fmaf(x0.z, w2v, a0); a1 = fmaf(x1.z, w2v, a1);
                    a0 = fmaf(x0.w, w3v, a0); a1 = fmaf(x1.w, w3v, a1);
                }
                float w64 = wcol[64 * 512];
                a0 = fmaf(xs[64], w64, a0);
                a1 = fmaf(xs[68 + 64], w64, a1);

                __nv_bfloat16* Hh = (__nv_bfloat16*)d_Hhi4;
                __nv_bfloat16* Hl = (__nv_bfloat16*)d_Hlo4;
                float v0 = tanhf(a0);
                float v1 = tanhf(a1);
                __nv_bfloat16 h0 = __float2bfloat16(v0);
                __nv_bfloat16 h1 = __float2bfloat16(v1);
                Hh[convb0 * 512 + t]       = h0;
                Hh[(convb0 + 1) * 512 + t] = h1;
                Hl[convb0 * 512 + t]       = __float2bfloat16(v0 - __bfloat162float(h0));
                Hl[(convb0 + 1) * 512 + t] = __float2bfloat16(v1 - __bfloat162float(h1));
            }
        }
        gbar(target += GRID);

        // ========== phase 2: HMMA GEMM (64 x 64, K=256, split-K x 2 warpsets) ==========
        if (is_sig) {   // dB staging
            int row = t >> 3, c = (t & 7) * 4;
            const float* src = &Bin[(size_t)(b0g + row) * ((NUMS + 1) * DIM)
                                    + (size_t)(j + 1) * DIM + c];
            float4 v = *(const float4*)src;
            if (j > 0) {
                float4 u = *(const float4*)(src - DIM);
                v.x -= u.x; v.y -= u.y; v.z -= u.z; v.w -= u.w;
            }
            dBs[row * 33 + c + 0] = v.x; dBs[row * 33 + c + 1] = v.y;
            dBs[row * 33 + c + 2] = v.z; dBs[row * 33 + c + 3] = v.w;
        }
        {   // A staging: H tile [64 x 256] hi+lo bf16 -> smem (8 parts of 128B)
            int row = t & 63, part = t >> 6;
            int isLo = part >> 2, quarter = part & 3;
            const uint4* src = (isLo ? d_Hlo4 : d_Hhi4)
                               + (b0g + row) * 64 + hofs4 + quarter * 8;
            char* dst = sm + (isLo ? OFF_ALO : OFF_AHI) + row * AP_B + quarter * 128;
            #pragma unroll
            for (int it = 0; it < 8; ++it) {
                uint4 v = __ldcg(src + it);
                *(uint4*)(dst + it * 16) = v;
            }
        }
        __syncthreads();

        float acc[2][2][4];
        #pragma unroll
        for (int mt = 0; mt < 2; ++mt)
            #pragma unroll
            for (int nt = 0; nt < 2; ++nt)
                #pragma unroll
                for (int q = 0; q < 4; ++q) acc[mt][nt][q] = 0.f;

        #pragma unroll
        for (int kt = 0; kt < 8; ++kt) {
            int ktg = kh * 8 + kt;
            uint32_t ah[2][4], al[2][4];
            #pragma unroll
            for (int mt = 0; mt < 2; ++mt) {
                ldsm4(aBaseHi + mt * (16 * AP_B) + ktg * 32, ah[mt]);
                ldsm4(aBaseLo + mt * (16 * AP_B) + ktg * 32, al[mt]);
            }
            #pragma unroll
            for (int mt = 0; mt < 2; ++mt)
                #pragma unroll
                for (int nt = 0; nt < 2; ++nt) {
                    mma16816(acc[mt][nt], ah[mt], Bhi[kt][nt][0], Bhi[kt][nt][1]);
                    mma16816(acc[mt][nt], ah[mt], Blo[kt][nt][0], Blo[kt][nt][1]);
                    mma16816(acc[mt][nt], al[mt], Bhi[kt][nt][0], Bhi[kt][nt][1]);
                }
        }

        // ---- split-K combine through Osm ----
        int rb  = wr * 32 + (lane >> 2);
        int cbc = wc * 16 + (lane & 3) * 2;
        if (kh == 0) {
            #pragma unroll
            for (int mt = 0; mt < 2; ++mt)
                #pragma unroll
                for (int nt = 0; nt < 2; ++nt) {
                    int row0 = rb + mt * 16, col = cbc + nt * 8;
                    Osm[row0 * 68 + col]           = acc[mt][nt][0] + biasS[col];
                    Osm[row0 * 68 + col + 1]       = acc[mt][nt][1] + biasS[col + 1];
                    Osm[(row0 + 8) * 68 + col]     = acc[mt][nt][2] + biasS[col];
                    Osm[(row0 + 8) * 68 + col + 1] = acc[mt][nt][3] + biasS[col + 1];
                }
        }
        __syncthreads();
        if (kh == 1) {
            #pragma unroll
            for (int mt = 0; mt < 2; ++mt)
                #pragma unroll
                for (int nt = 0; nt < 2; ++nt) {
                    int row0 = rb + mt * 16, col = cbc + nt * 8;
                    Osm[row0 * 68 + col]           += acc[mt][nt][0];
                    Osm[row0 * 68 + col + 1]       += acc[mt][nt][1];
                    Osm[(row0 + 8) * 68 + col]     += acc[mt][nt][2];
                    Osm[(row0 + 8) * 68 + col + 1] += acc[mt][nt][3];
                }
        }
        __syncthreads();

        if (is_sig) {
            if (t < 128) {
                int row = t >> 1, hh = t & 1;
                const float* orow = &Osm[row * 68 + hh * 32];
                const float* drow = &dBs[row * 33];
                float s = 0.f;
                #pragma unroll 8
                for (int d = 0; d < 32; ++d) s = fmaf(orow[d], drow[d], s);
                d_svh[(size_t)j * (BATCH * HCH) + (b0g + row) * HCH + cb * 2 + hh] = s;
            }
        } else {
            int row = t >> 3, c0m = (t & 7) * 8;
            float* dst = &d_muh[(size_t)j * (BATCH * HCH) + (b0g + row) * HCH + c0m];
            *(float4*)dst       = *(const float4*)&Osm[row * 68 + c0m];
            *(float4*)(dst + 4) = *(const float4*)&Osm[row * 68 + c0m + 4];
        }
        gbar(target += GRID);
    }

    // ---- final output row 128 (conv only) ----
    if (is_sig) {
        if (t < 128) { kwv[t] = DT * d_kmu[NUMS - t]; ksv[t] = d_ksig[NUMS - t]; }
        __syncthreads();
        int e = t & 127, p = t >> 7;
        float acc = 0.f;
        int base = convb0 * HCH + e;
        #pragma unroll 4
        for (int m = p; m < NUMS; m += 4)
            acc += kwv[m] * d_muh[m * (BATCH * HCH) + base]
                 + ksv[m] * d_svh[m * (BATCH * HCH) + base];
        red[t] = acc;
        __syncthreads();
        if (t < 128) {
            float s = red[t] + red[t + 128] + red[t + 256] + red[t + 384];
            float z = z0[convb0 * HCH + t];
            out[(size_t)NUMS * (BATCH * HCH) + convb0 * HCH + t] = z * d_gvals[NUMS] + s;
        }
    }
}

// ---------------- launch ----------------
extern "C" void kernel_launch(void* const* d_in, const int* in_sizes, int n_in,
                              void* d_out, int out_size)
{
    const float* B    = (const float*)d_in[0];
    const float* z0   = (const float*)d_in[1];
    const float* gw1  = (const float*)d_in[6];
    const float* gb1  = (const float*)d_in[7];
    const float* gw2  = (const float*)d_in[8];
    const float* gb2  = (const float*)d_in[9];
    const float* kmw1 = (const float*)d_in[10];
    const float* kmb1 = (const float*)d_in[11];
    const float* kmw2 = (const float*)d_in[12];
    const float* kmb2 = (const float*)d_in[13];
    const float* ksw1 = (const float*)d_in[14];
    const float* ksb1 = (const float*)d_in[15];
    const float* ksw2 = (const float*)d_in[16];
    const float* ksb2 = (const float*)d_in[17];
    const float* muw1 = (const float*)d_in[18];
    const float* mub1 = (const float*)d_in[19];
    const float* muw2 = (const float*)d_in[20];
    const float* mub2 = (const float*)d_in[21];
    const float* sgw1 = (const float*)d_in[22];
    const float* sgb1 = (const float*)d_in[23];
    const float* sgw2 = (const float*)d_in[24];
    const float* sgb2 = (const float*)d_in[25];
    float* out = (float*)d_out;

    cudaFuncSetAttribute(solve, cudaFuncAttributeMaxDynamicSharedMemorySize, SMEM_BYTES);

    init_kernel<<<1, 256>>>(gw1, gb1, gw2, gb2, kmw1, kmb1, kmw2, kmb2,
                            ksw1, ksb1, ksw2, ksb2);
    solve<<<GRID, TPB, SMEM_BYTES>>>(B, z0, muw1, mub1, muw2, mub2,
                                     sgw1, sgb1, sgw2, sgb2, out);
}

// round 17
// speedup vs baseline: 1.6999x; 1.0799x over previous
#include <cuda_runtime.h>
#include <cuda_bf16.h>
#include <math.h>
#include <stdint.h>

#define NUMS  128
#define BATCH 256
#define HCH   64
#define DIM   32
#define HID   256
#define XDIM  65
#define KW    32
#define DT    (1.0f/128.0f)
#define GRID  132
#define TPB   512

#define AP_B 528            // A smem row stride in bytes (264 bf16)

// smem byte offsets
#define OFF_W1   0                       // 65 x 512 f32 = 133120 (combined mu|sig w1)
#define OFF_AHI  133120                  // 64 x 528B = 33792
#define OFF_ALO  166912
#define OFF_OS   200704                  // 64 x 68 f32 = 17408
#define OFF_DB   218112                  // 64 x 33 f32 = 8448
#define OFF_BIAS 226560                  // 64 f32
#define SMEM_BYTES 226816
// phase-1/window scratch overlaid into the Osm region (time-disjoint with Osm)
#define OFF_XS   (OFF_OS + 0)            // 2 x 68 f32
#define OFF_KWV  (OFF_OS + 1024)         // 128 f32
#define OFF_KSV  (OFF_OS + 1536)         // 128 f32
#define OFF_RED  (OFF_OS + 2048)         // 512 f32 -> ends OS+4096

// ---------------- device scratch ----------------
__device__ float d_gvals[NUMS + 1];
__device__ float d_kmu[NUMS + 1];
__device__ float d_ksig[NUMS + 1];
__device__ uint4 d_Hhi4[BATCH * 64];    // 256 rows x 512 bf16-hi
__device__ uint4 d_Hlo4[BATCH * 64];
__device__ float d_muh[NUMS * BATCH * HCH];
__device__ float d_svh[NUMS * BATCH * HCH];
__device__ unsigned d_bar;

// ---------------- init ----------------
__global__ void init_kernel(const float* gw1, const float* gb1, const float* gw2, const float* gb2,
                            const float* mw1, const float* mb1, const float* mw2, const float* mb2,
                            const float* sw1, const float* sb1, const float* sw2, const float* sb2)
{
    int t = threadIdx.x;
    if (t == 0) d_bar = 0u;
    if (t <= NUMS) {
        float tt = t * DT;
        float a = gb2[0], b = mb2[0], c = sb2[0];
        for (int k = 0; k < KW; ++k) {
            a += tanhf(tt * gw1[k] + gb1[k]) * gw2[k];
            b += tanhf(tt * mw1[k] + mb1[k]) * mw2[k];
            c += tanhf(tt * sw1[k] + sb1[k]) * sw2[k];
        }
        d_gvals[t] = a; d_kmu[t] = b; d_ksig[t] = c;
    }
}

// ---------------- helpers ----------------
static __device__ __forceinline__ uint32_t s2u(const void* p) {
    uint32_t a;
    asm("{ .reg .u64 t; cvta.to.shared.u64 t, %1; cvt.u32.u64 %0, t; }" : "=r"(a) : "l"(p));
    return a;
}
static __device__ __forceinline__ void gbar_arrive() {
    __syncthreads();
    if (threadIdx.x == 0) {
        unsigned* p = &d_bar;
        asm volatile("red.release.gpu.global.add.u32 [%0], 1;" :: "l"(p) : "memory");
    }
}
static __device__ __forceinline__ void gbar_wait(unsigned target) {
    if (threadIdx.x == 0) {
        unsigned* p = &d_bar;
        unsigned v;
        do {
            asm volatile("ld.acquire.gpu.global.u32 %0, [%1];" : "=r"(v) : "l"(p) : "memory");
        } while ((int)(v - target) < 0);
    }
    __syncthreads();
}
static __device__ __forceinline__ void ldsm4(uint32_t addr, uint32_t* r) {
    asm volatile("ldmatrix.sync.aligned.m8n8.x4.shared.b16 {%0,%1,%2,%3}, [%4];"
                 : "=r"(r[0]), "=r"(r[1]), "=r"(r[2]), "=r"(r[3]) : "r"(addr));
}
static __device__ __forceinline__ void mma16816(float* c, const uint32_t* a,
                                                uint32_t b0, uint32_t b1) {
    asm volatile("mma.sync.aligned.m16n8k16.row.col.f32.bf16.bf16.f32 "
                 "{%0,%1,%2,%3}, {%4,%5,%6,%7}, {%8,%9}, {%0,%1,%2,%3};"
                 : "+f"(c[0]), "+f"(c[1]), "+f"(c[2]), "+f"(c[3])
                 : "r"(a[0]), "r"(a[1]), "r"(a[2]), "r"(a[3]), "r"(b0), "r"(b1));
}
static __device__ __forceinline__ unsigned packbf(float x, float y) {
    __nv_bfloat16 bx = __float2bfloat16(x), by = __float2bfloat16(y);
    return ((unsigned)__bfloat16_as_ushort(by) << 16) | __bfloat16_as_ushort(bx);
}

// ---------------- persistent solver ----------------
__global__ void __launch_bounds__(TPB, 1) solve(
    const float* __restrict__ Bin, const float* __restrict__ z0,
    const float* __restrict__ muw1, const float* __restrict__ mub1,
    const float* __restrict__ muw2, const float* __restrict__ mub2,
    const float* __restrict__ sgw1, const float* __restrict__ sgb1,
    const float* __restrict__ sgw2, const float* __restrict__ sgb2,
    float* __restrict__ out)
{
    extern __shared__ __align__(16) char sm[];
    uint32_t smb = s2u(sm);
    float* w1s   = (float*)(sm + OFF_W1);
    float* Osm   = (float*)(sm + OFF_OS);
    float* dBs   = (float*)(sm + OFF_DB);
    float* biasS = (float*)(sm + OFF_BIAS);
    float* xs    = (float*)(sm + OFF_XS);
    float* kwv   = (float*)(sm + OFF_KWV);
    float* ksv   = (float*)(sm + OFF_KSV);
    float* red   = (float*)(sm + OFF_RED);

    int bk = blockIdx.x, t = threadIdx.x;
    int wid = t >> 5, lane = t & 31;
    unsigned target = 0;

    bool is_sig = (bk < 128);
    int b0g  = is_sig ? (bk >> 5) * 64 : (bk - 128) * 64;
    int cb   = is_sig ? (bk & 31) : 0;
    int col0 = cb * 64;
    const float* W2  = is_sig ? sgw2 : muw2;
    const float* B2b = is_sig ? (sgb2 + col0) : mub2;
    int ldw   = is_sig ? (HCH * DIM) : HCH;
    int hofs4 = is_sig ? 32 : 0;

    if (t < 64) biasS[t] = B2b[t];

    // ---- w1 (mu|sig combined) into smem ONCE ----
    for (int idx = t; idx < 65 * 512; idx += TPB) {
        int i = idx >> 9, c = idx & 511;
        w1s[idx] = (c < 256) ? muw1[i * 256 + c] : sgw1[i * 256 + (c - 256)];
    }
    float b1c = (t < 256) ? mub1[t] : sgb1[t - 256];
    float kmu1 = DT * d_kmu[1];
    float ksg1 = d_ksig[1];

    // ---- warp mapping: 2 K-halves x (4 col-groups x 2 row-groups) ----
    int kh   = wid >> 3;
    int wsub = wid & 7;
    int wc = wsub & 3, wr = wsub >> 2;

    // ---- B fragments (W2 slice) in registers, hi/lo, this K-half only ----
    unsigned Bhi[8][2][2], Blo[8][2][2];
    {
        int nb = col0 + wc * 16 + (lane >> 2);
        #pragma unroll
        for (int kt = 0; kt < 8; ++kt)
            #pragma unroll
            for (int nt = 0; nt < 2; ++nt)
                #pragma unroll
                for (int rr = 0; rr < 2; ++rr) {
                    int k0 = (kh * 8 + kt) * 16 + (lane & 3) * 2 + rr * 8;
                    int n  = nb + nt * 8;
                    float w0 = W2[(size_t)k0 * ldw + n];
                    float w1 = W2[(size_t)(k0 + 1) * ldw + n];
                    __nv_bfloat16 h0 = __float2bfloat16(w0);
                    __nv_bfloat16 h1 = __float2bfloat16(w1);
                    float l0 = w0 - __bfloat162float(h0);
                    float l1 = w1 - __bfloat162float(h1);
                    Bhi[kt][nt][rr] = ((unsigned)__bfloat16_as_ushort(h1) << 16)
                                    | __bfloat16_as_ushort(h0);
                    Blo[kt][nt][rr] = packbf(l0, l1);
                }
    }

    int convb0 = bk * 2;
    uint32_t aBaseHi = smb + OFF_AHI + (wr * 32 + (lane & 15)) * AP_B + ((lane >> 4) * 8) * 2;
    uint32_t aBaseLo = aBaseHi + (uint32_t)(OFF_ALO - OFF_AHI);

    float Preg = 0.f;   // conv partial for step j over m <= j-2, held across phases

    for (int j = 0; j < NUMS; ++j) {
        // ========== phase 1': finish S_j, MLP1 -> packed hi/lo H ==========
        if (is_sig) {
            red[t] = Preg;
            if (t < 2) xs[t * 68] = j * DT;
            __syncthreads();

            if (t < 128) {
                float s = red[t] + red[t + 128] + red[t + 256] + red[t + 384];
                int base = convb0 * HCH + t;
                float z = z0[base];
                float S = z * d_gvals[j] + s;
                if (j > 0)
                    S += kmu1 * d_muh[(j - 1) * (BATCH * HCH) + base]
                       + ksg1 * d_svh[(j - 1) * (BATCH * HCH) + base];
                out[(size_t)j * (BATCH * HCH) + base] = S;
                xs[(t >> 6) * 68 + 1 + (t & 63)] = (j == 0) ? z : S;
            }
            __syncthreads();

            // MLP1: thread t -> combined col t (0..511), BOTH rows (w1 read once)
            {
                const float* wcol = w1s + t;
                float a0 = b1c, a1 = b1c;
                #pragma unroll
                for (int i4 = 0; i4 < 64; i4 += 4) {
                    float4 x0 = *(const float4*)&xs[i4];
                    float4 x1 = *(const float4*)&xs[68 + i4];
                    float w0 = wcol[(i4 + 0) * 512];
                    float w1v = wcol[(i4 + 1) * 512];
                    float w2v = wcol[(i4 + 2) * 512];
                    float w3v = wcol[(i4 + 3) * 512];
                    a0 = fmaf(x0.x, w0, a0); a1 = fmaf(x1.x, w0, a1);
                    a0 = fmaf(x0.y, w1v, a0); a1 = fmaf(x1.y, w1v, a1);
                    a0 = fmaf(x0.z, w2v, a0); a1 = fmaf(x1.z, w2v, a1);
                    a0 = fmaf(x0.w, w3v, a0); a1 = fmaf(x1.w, w3v, a1);
                }
                float w64 = wcol[64 * 512];
                a0 = fmaf(xs[64], w64, a0);
                a1 = fmaf(xs[68 + 64], w64, a1);

                __nv_bfloat16* Hh = (__nv_bfloat16*)d_Hhi4;
                __nv_bfloat16* Hl = (__nv_bfloat16*)d_Hlo4;
                float v0 = tanhf(a0);
                float v1 = tanhf(a1);
                __nv_bfloat16 h0 = __float2bfloat16(v0);
                __nv_bfloat16 h1 = __float2bfloat16(v1);
                Hh[convb0 * 512 + t]       = h0;
                Hh[(convb0 + 1) * 512 + t] = h1;
                Hl[convb0 * 512 + t]       = __float2bfloat16(v0 - __bfloat162float(h0));
                Hl[(convb0 + 1) * 512 + t] = __float2bfloat16(v1 - __bfloat162float(h1));
            }
        }
        gbar_arrive();
        target += GRID;

        // ========== window (overlapped with barrier wait): ==========
        // kwv for step j+1, dB staging for step j, conv partial P_{j+1} (m <= j-1)
        Preg = 0.f;
        if (is_sig) {
            if (t < j) { kwv[t] = DT * d_kmu[j + 1 - t]; ksv[t] = d_ksig[j + 1 - t]; }
            {   // dB staging
                int row = t >> 3, c = (t & 7) * 4;
                const float* src = &Bin[(size_t)(b0g + row) * ((NUMS + 1) * DIM)
                                        + (size_t)(j + 1) * DIM + c];
                float4 v = *(const float4*)src;
                if (j > 0) {
                    float4 u = *(const float4*)(src - DIM);
                    v.x -= u.x; v.y -= u.y; v.z -= u.z; v.w -= u.w;
                }
                dBs[row * 33 + c + 0] = v.x; dBs[row * 33 + c + 1] = v.y;
                dBs[row * 33 + c + 2] = v.z; dBs[row * 33 + c + 3] = v.w;
            }
            __syncthreads();

            int e = t & 127, p = t >> 7;     // 4-way k-split
            int base = convb0 * HCH + e;
            #pragma unroll 4
            for (int m = p; m < j; m += 4)
                Preg += kwv[m] * d_muh[m * (BATCH * HCH) + base]
                      + ksv[m] * d_svh[m * (BATCH * HCH) + base];
        }
        gbar_wait(target);

        // ========== phase 2: HMMA GEMM (64 x 64, K=256, split-K x 2 warpsets) ==========
        {   // A staging: H tile [64 x 256] hi+lo bf16 -> smem (8 parts of 128B)
            int row = t & 63, part = t >> 6;
            int isLo = part >> 2, quarter = part & 3;
            const uint4* src = (isLo ? d_Hlo4 : d_Hhi4)
                               + (b0g + row) * 64 + hofs4 + quarter * 8;
            char* dst = sm + (isLo ? OFF_ALO : OFF_AHI) + row * AP_B + quarter * 128;
            #pragma unroll
            for (int it = 0; it < 8; ++it) {
                uint4 v = __ldcg(src + it);
                *(uint4*)(dst + it * 16) = v;
            }
        }
        __syncthreads();

        float acc[2][2][4];
        #pragma unroll
        for (int mt = 0; mt < 2; ++mt)
            #pragma unroll
            for (int nt = 0; nt < 2; ++nt)
                #pragma unroll
                for (int q = 0; q < 4; ++q) acc[mt][nt][q] = 0.f;

        #pragma unroll
        for (int kt = 0; kt < 8; ++kt) {
            int ktg = kh * 8 + kt;
            uint32_t ah[2][4], al[2][4];
            #pragma unroll
            for (int mt = 0; mt < 2; ++mt) {
                ldsm4(aBaseHi + mt * (16 * AP_B) + ktg * 32, ah[mt]);
                ldsm4(aBaseLo + mt * (16 * AP_B) + ktg * 32, al[mt]);
            }
            #pragma unroll
            for (int mt = 0; mt < 2; ++mt)
                #pragma unroll
                for (int nt = 0; nt < 2; ++nt) {
                    mma16816(acc[mt][nt], ah[mt], Bhi[kt][nt][0], Bhi[kt][nt][1]);
                    mma16816(acc[mt][nt], ah[mt], Blo[kt][nt][0], Blo[kt][nt][1]);
                    mma16816(acc[mt][nt], al[mt], Bhi[kt][nt][0], Bhi[kt][nt][1]);
                }
        }

        // ---- split-K combine through Osm ----
        int rb  = wr * 32 + (lane >> 2);
        int cbc = wc * 16 + (lane & 3) * 2;
        if (kh == 0) {
            #pragma unroll
            for (int mt = 0; mt < 2; ++mt)
                #pragma unroll
                for (int nt = 0; nt < 2; ++nt) {
                    int row0 = rb + mt * 16, col = cbc + nt * 8;
                    Osm[row0 * 68 + col]           = acc[mt][nt][0] + biasS[col];
                    Osm[row0 * 68 + col + 1]       = acc[mt][nt][1] + biasS[col + 1];
                    Osm[(row0 + 8) * 68 + col]     = acc[mt][nt][2] + biasS[col];
                    Osm[(row0 + 8) * 68 + col + 1] = acc[mt][nt][3] + biasS[col + 1];
                }
        }
        __syncthreads();
        if (kh == 1) {
            #pragma unroll
            for (int mt = 0; mt < 2; ++mt)
                #pragma unroll
                for (int nt = 0; nt < 2; ++nt) {
                    int row0 = rb + mt * 16, col = cbc + nt * 8;
                    Osm[row0 * 68 + col]           += acc[mt][nt][0];
                    Osm[row0 * 68 + col + 1]       += acc[mt][nt][1];
                    Osm[(row0 + 8) * 68 + col]     += acc[mt][nt][2];
                    Osm[(row0 + 8) * 68 + col + 1] += acc[mt][nt][3];
                }
        }
        __syncthreads();

        if (is_sig) {
            if (t < 128) {
                int row = t >> 1, hh = t & 1;
                const float* orow = &Osm[row * 68 + hh * 32];
                const float* drow = &dBs[row * 33];
                float s = 0.f;
                #pragma unroll 8
                for (int d = 0; d < 32; ++d) s = fmaf(orow[d], drow[d], s);
                d_svh[(size_t)j * (BATCH * HCH) + (b0g + row) * HCH + cb * 2 + hh] = s;
            }
        } else {
            int row = t >> 3, c0m = (t & 7) * 8;
            float* dst = &d_muh[(size_t)j * (BATCH * HCH) + (b0g + row) * HCH + c0m];
            *(float4*)dst       = *(const float4*)&Osm[row * 68 + c0m];
            *(float4*)(dst + 4) = *(const float4*)&Osm[row * 68 + c0m + 4];
        }
        gbar_arrive();
        target += GRID;
        gbar_wait(target);
    }

    // ---- final output row 128: P_128 (m<=126) + last term (m=127) ----
    if (is_sig) {
        red[t] = Preg;
        __syncthreads();
        if (t < 128) {
            float s = red[t] + red[t + 128] + red[t + 256] + red[t + 384];
            int base = convb0 * HCH + t;
            float z = z0[base];
            float S = z * d_gvals[NUMS] + s
                    + kmu1 * d_muh[(NUMS - 1) * (BATCH * HCH) + base]
                    + ksg1 * d_svh[(NUMS - 1) * (BATCH * HCH) + base];
            out[(size_t)NUMS * (BATCH * HCH) + base] = S;
        }
    }
}

// ---------------- launch ----------------
extern "C" void kernel_launch(void* const* d_in, const int* in_sizes, int n_in,
                              void* d_out, int out_size)
{
    const float* B    = (const float*)d_in[0];
    const float* z0   = (const float*)d_in[1];
    const float* gw1  = (const float*)d_in[6];
    const float* gb1  = (const float*)d_in[7];
    const float* gw2  = (const float*)d_in[8];
    const float* gb2  = (const float*)d_in[9];
    const float* kmw1 = (const float*)d_in[10];
    const float* kmb1 = (const float*)d_in[11];
    const float* kmw2 = (const float*)d_in[12];
    const float* kmb2 = (const float*)d_in[13];
    const float* ksw1 = (const float*)d_in[14];
    const float* ksb1 = (const float*)d_in[15];
    const float* ksw2 = (const float*)d_in[16];
    const float* ksb2 = (const float*)d_in[17];
    const float* muw1 = (const float*)d_in[18];
    const float* mub1 = (const float*)d_in[19];
    const float* muw2 = (const float*)d_in[20];
    const float* mub2 = (const float*)d_in[21];
    const float* sgw1 = (const float*)d_in[22];
    const float* sgb1 = (const float*)d_in[23];
    const float* sgw2 = (const float*)d_in[24];
    const float* sgb2 = (const float*)d_in[25];
    float* out = (float*)d_out;

    cudaFuncSetAttribute(solve, cudaFuncAttributeMaxDynamicSharedMemorySize, SMEM_BYTES);

    init_kernel<<<1, 256>>>(gw1, gb1, gw2, gb2, kmw1, kmb1, kmw2, kmb2,
                            ksw1, ksb1, ksw2, ksb2);
    solve<<<GRID, TPB, SMEM_BYTES>>>(B, z0, muw1, mub1, muw2, mub2,
                                     sgw1, sgb1, sgw2, sgb2, out);
}